// round 5
// baseline (speedup 1.0000x reference)
#include <cuda_runtime.h>
#include <cstdint>

// Problem dims
#define S_LEN 1024
#define B_DIM 256
#define E_DIM 128
#define H_DIM 256
#define O_DIM 2
#define K_DIM (E_DIM + H_DIM)   // 384

// Decomposition: 8 batch groups x 16 hidden groups = 128 CTAs (1 per SM)
// Each batch group = one 16-CTA cluster.
#define GB 8
#define GC 16
#define NCTA (GB * GC)
#define BT (B_DIM / GB)          // 32 batch rows per CTA
#define HS (H_DIM / GC)          // 16 hidden units per CTA
#define GT (4 * HS)              // 64 gate columns per CTA
#define NTHR 256

// GEMM warp layout: 4 k-split groups x 2 n-halves (fat warps: m32 x n32 each)
#define KS 4
#define NXT 4                    // x-part k-tiles per warp
#define NHT 8                    // h-part k-tiles per warp
#define NKT (NXT + NHT)          // 12

// SMEM strides (padded for bank-conflict-free mma fragment loads)
#define WT_ST 72
#define ACT_ST 388
#define G_ST 72

#define SMEM_F32 (K_DIM*WT_ST + BT*ACT_ST + KS*BT*G_ST + BT*HS + GT + BT + BT + 4)
#define SMEM_BYTES (SMEM_F32 * 4)
static_assert(SMEM_BYTES <= 227 * 1024, "smem too big");

// Global scratch: double-buffered hidden state (tf32-rounded fp32 bits)
__device__ float g_h[2][B_DIM][H_DIM];

__device__ __forceinline__ unsigned f2tf(float x) {
    unsigned u; asm("cvt.rna.tf32.f32 %0, %1;" : "=r"(u) : "f"(x)); return u;
}
__device__ __forceinline__ float sigf(float x) {
    return __fdividef(1.0f, 1.0f + __expf(-x));
}
__device__ __forceinline__ float tanhfast(float x) {
    return 2.0f * __fdividef(1.0f, 1.0f + __expf(-2.0f * x)) - 1.0f;
}

__device__ __forceinline__ void mma8(float& d0, float& d1, float& d2, float& d3,
                                     unsigned a0, unsigned a1, unsigned a2, unsigned a3,
                                     unsigned b0, unsigned b1) {
    asm volatile(
        "mma.sync.aligned.m16n8k8.row.col.f32.tf32.tf32.f32 "
        "{%0,%1,%2,%3},{%4,%5,%6,%7},{%8,%9},{%0,%1,%2,%3};"
        : "+f"(d0), "+f"(d1), "+f"(d2), "+f"(d3)
        : "r"(a0), "r"(a1), "r"(a2), "r"(a3), "r"(b0), "r"(b1));
}

#define CP_ASYNC16(dst_u32, src) \
    asm volatile("cp.async.cg.shared.global [%0], [%1], 16;" :: "r"(dst_u32), "l"(src))
#define CP_COMMIT() asm volatile("cp.async.commit_group;")
#define CP_WAIT0()  asm volatile("cp.async.wait_group 0;")

// One arrive to the same-offset mbarrier in cluster CTA `rank` (release, cluster scope).
__device__ __forceinline__ void mbar_arrive_rank(unsigned mbar_addr, unsigned rank) {
    asm volatile(
        "{\n\t.reg .b32 ra;\n\t"
        "mapa.shared::cluster.u32 ra, %0, %1;\n\t"
        "mbarrier.arrive.release.cluster.shared::cluster.b64 _, [ra];\n\t}"
        :: "r"(mbar_addr), "r"(rank) : "memory");
}

// Spin on local mbarrier phase parity (acquire, cluster scope).
__device__ __forceinline__ void mbar_wait(unsigned mbar_addr, unsigned parity) {
    asm volatile(
        "{\n\t.reg .pred P;\n\t"
        "W_%=:\n\t"
        "mbarrier.try_wait.parity.acquire.cluster.shared::cta.b64 P, [%0], %1, 0x989680;\n\t"
        "@P bra D_%=;\n\t"
        "bra W_%=;\n\t"
        "D_%=:\n\t}"
        :: "r"(mbar_addr), "r"(parity) : "memory");
}

__global__ void __launch_bounds__(NTHR, 1) __cluster_dims__(GC, 1, 1)
lstm_kernel(const int* __restrict__ inp, const int* __restrict__ lengths,
            const float* __restrict__ h0, const float* __restrict__ c0,
            const float* __restrict__ emb, const float* __restrict__ w_ih,
            const float* __restrict__ w_hh, const float* __restrict__ b_ih,
            const float* __restrict__ b_hh, const float* __restrict__ dec_w,
            float* __restrict__ out) {
    extern __shared__ float sm[];
    float* sW    = sm;                         // [K_DIM][WT_ST]
    float* sA    = sW + K_DIM * WT_ST;         // [BT][ACT_ST]
    float* sG    = sA + BT * ACT_ST;           // [KS][BT][G_ST] gate partials
    float* sC    = sG + KS * BT * G_ST;        // [BT][HS]
    float* sBias = sC + BT * HS;               // [GT]
    int*   sLen  = (int*)(sBias + GT);         // [BT]
    int*   sTok  = sLen + BT;                  // [BT]
    int*   sMax  = sTok + BT;                  // [1]

    __shared__ __align__(8) unsigned long long smBar;   // cluster step barrier
    const unsigned barAddr = (unsigned)__cvta_generic_to_shared(&smBar);

    const int tid = threadIdx.x;
    const int cta = blockIdx.x;
    const int gb = cta / GC;
    const int gc = cta % GC;                   // == cluster rank
    const int b0 = gb * BT;

    // ---- one-time init: weights (tf32), bias, lengths, c state, h[0] ----
    for (int idx = tid; idx < K_DIM * GT; idx += NTHR) {
        int k = idx / GT, c = idx % GT;
        int grow = (c / HS) * H_DIM + gc * HS + (c % HS);   // gate order i,f,g,o
        float w = (k < E_DIM) ? w_ih[grow * E_DIM + k] : w_hh[grow * H_DIM + (k - E_DIM)];
        sW[k * WT_ST + c] = __uint_as_float(f2tf(w));
    }
    if (tid < GT) {
        int grow = (tid / HS) * H_DIM + gc * HS + (tid % HS);
        sBias[tid] = b_ih[grow] + b_hh[grow];
    }
    if (tid < BT) sLen[tid] = lengths[b0 + tid];
    for (int idx = tid; idx < BT * HS; idx += NTHR) {
        int m = idx / HS, u = idx % HS;
        sC[idx] = c0[(b0 + m) * H_DIM + gc * HS + u];
    }
    if (gc == 0) {
        for (int idx = tid; idx < BT * H_DIM; idx += NTHR) {
            int m = idx / H_DIM, u = idx % H_DIM;
            g_h[0][b0 + m][u] = __uint_as_float(f2tf(h0[(b0 + m) * H_DIM + u]));
        }
    }
    if (tid < BT) sTok[tid] = inp[b0 + tid];   // tokens for t = 0
    if (tid == 0) {
        asm volatile("mbarrier.init.shared.b64 [%0], %1;" :: "r"(barAddr), "r"((unsigned)GC) : "memory");
    }
    __syncthreads();
    if (tid == 0) {
        int mx = 0;
        for (int i = 0; i < BT; ++i) mx = max(mx, sLen[i]);
        sMax[0] = mx;
    }
    __syncthreads();
    const int ctaMax = sMax[0];                // uniform across the cluster (same rows)

    const int lane = tid & 31, warp = tid >> 5;
    const int ng = warp & 1;      // n half: 32 cols
    const int ks = warp >> 1;     // k slice

    // ---- preload this warp's B fragments into registers (step-invariant) ----
    unsigned bw[NKT][4][2];
    #pragma unroll
    for (int i = 0; i < NKT; ++i) {
        int ktg = (i < NXT) ? (ks * NXT + i) : (16 + ks * NHT + (i - NXT));
        const float* Bk = &sW[(ktg * 8 + (lane & 3)) * WT_ST + ng * 32 + (lane >> 2)];
        #pragma unroll
        for (int j = 0; j < 4; ++j) {
            bw[i][j][0] = __float_as_uint(Bk[j * 8]);
            bw[i][j][1] = __float_as_uint(Bk[4 * WT_ST + j * 8]);
        }
    }

    // prologue: embedding columns of sA for t = 0
    #pragma unroll
    for (int rep = 0; rep < (BT * 32) / NTHR; ++rep) {
        int i4 = tid + rep * NTHR;
        int m = i4 >> 5, q = i4 & 31;
        float4 v = __ldg(reinterpret_cast<const float4*>(emb + (size_t)sTok[m] * E_DIM) + q);
        v.x = __uint_as_float(f2tf(v.x));
        v.y = __uint_as_float(f2tf(v.y));
        v.z = __uint_as_float(f2tf(v.z));
        v.w = __uint_as_float(f2tf(v.w));
        *reinterpret_cast<float4*>(&sA[m * ACT_ST + q * 4]) = v;
    }
    // cluster-wide: mbarrier inits + g_h[0] visible before anyone proceeds
    asm volatile("barrier.cluster.arrive.aligned;" ::: "memory");
    asm volatile("barrier.cluster.wait.aligned;" ::: "memory");
    __syncthreads();

    unsigned parity = 0;

    // ---- recurrence (cluster-local; early exit at group max length) ----
    for (int t = 0; t < ctaMax; ++t) {
        const int cur = t & 1, nxt = cur ^ 1;

        // phase 1a: issue async h[t] gather into sA cols 128..383 (no reg landing)
        #pragma unroll
        for (int rep = 0; rep < (BT * 64) / NTHR; ++rep) {
            int i4 = tid + rep * NTHR;
            int m = i4 >> 6, q = i4 & 63;
            unsigned dst = (unsigned)__cvta_generic_to_shared(&sA[m * ACT_ST + 128 + q * 4]);
            CP_ASYNC16(dst, &g_h[cur][b0 + m][q * 4]);
        }
        CP_COMMIT();
        // prefetch next tokens (independent)
        if (tid < BT && t + 1 < ctaMax) sTok[tid] = inp[(t + 1) * B_DIM + b0 + tid];

        // phase 1b: x-part GEMM (emb columns prefetched last step) while gather flies
        float acc[2][4][4] = {};
        const float* Ab = &sA[(lane >> 2) * ACT_ST + (lane & 3)];
        #pragma unroll
        for (int i = 0; i < NXT; ++i) {
            const int kk = (ks * NXT + i) * 8;
            unsigned a[2][4];
            #pragma unroll
            for (int mg = 0; mg < 2; ++mg) {
                const float* Ak = Ab + mg * 16 * ACT_ST + kk;
                a[mg][0] = __float_as_uint(Ak[0]);
                a[mg][1] = __float_as_uint(Ak[8 * ACT_ST]);
                a[mg][2] = __float_as_uint(Ak[4]);
                a[mg][3] = __float_as_uint(Ak[8 * ACT_ST + 4]);
            }
            #pragma unroll
            for (int j = 0; j < 4; ++j) {
                mma8(acc[0][j][0], acc[0][j][1], acc[0][j][2], acc[0][j][3],
                     a[0][0], a[0][1], a[0][2], a[0][3], bw[i][j][0], bw[i][j][1]);
                mma8(acc[1][j][0], acc[1][j][1], acc[1][j][2], acc[1][j][3],
                     a[1][0], a[1][1], a[1][2], a[1][3], bw[i][j][0], bw[i][j][1]);
            }
        }
        CP_WAIT0();
        __syncthreads();

        // phase 2: h-part GEMM (k = 128..383)
        #pragma unroll
        for (int i = 0; i < NHT; ++i) {
            const int kk = (16 + ks * NHT + i) * 8;
            unsigned a[2][4];
            #pragma unroll
            for (int mg = 0; mg < 2; ++mg) {
                const float* Ak = Ab + mg * 16 * ACT_ST + kk;
                a[mg][0] = __float_as_uint(Ak[0]);
                a[mg][1] = __float_as_uint(Ak[8 * ACT_ST]);
                a[mg][2] = __float_as_uint(Ak[4]);
                a[mg][3] = __float_as_uint(Ak[8 * ACT_ST + 4]);
            }
            #pragma unroll
            for (int j = 0; j < 4; ++j) {
                mma8(acc[0][j][0], acc[0][j][1], acc[0][j][2], acc[0][j][3],
                     a[0][0], a[0][1], a[0][2], a[0][3], bw[NXT + i][j][0], bw[NXT + i][j][1]);
                mma8(acc[1][j][0], acc[1][j][1], acc[1][j][2], acc[1][j][3],
                     a[1][0], a[1][1], a[1][2], a[1][3], bw[NXT + i][j][0], bw[NXT + i][j][1]);
            }
        }
        {   // spill gate partial tile to smem
            float* sGp = sG + ks * BT * G_ST;
            #pragma unroll
            for (int mg = 0; mg < 2; ++mg) {
                int r = mg * 16 + (lane >> 2);
                #pragma unroll
                for (int j = 0; j < 4; ++j) {
                    int cb = ng * 32 + j * 8 + 2 * (lane & 3);
                    sGp[r * G_ST + cb]           = acc[mg][j][0];
                    sGp[r * G_ST + cb + 1]       = acc[mg][j][1];
                    sGp[(r + 8) * G_ST + cb]     = acc[mg][j][2];
                    sGp[(r + 8) * G_ST + cb + 1] = acc[mg][j][3];
                }
            }
        }
        __syncthreads();

        // phase 3: elementwise cell update (+ partial-sum combine)
        #pragma unroll
        for (int rep = 0; rep < (BT * HS) / NTHR; ++rep) {
            int idx = tid + rep * NTHR;
            int m = idx >> 4, u = idx & 15;
            float xi = sBias[u], xf = sBias[HS + u], xg = sBias[2 * HS + u], xo = sBias[3 * HS + u];
            #pragma unroll
            for (int p = 0; p < KS; ++p) {
                const float* gm = &sG[p * BT * G_ST + m * G_ST];
                xi += gm[u];
                xf += gm[HS + u];
                xg += gm[2 * HS + u];
                xo += gm[3 * HS + u];
            }
            float ii = sigf(xi), ff = sigf(xf), gg = tanhfast(xg), oo = sigf(xo);
            float c = ff * sC[idx] + ii * gg;
            sC[idx] = c;
            float h = oo * tanhfast(c);
            int b = b0 + m, ug = gc * HS + u;
            g_h[nxt][b][ug] = __uint_as_float(f2tf(h));
            if (t == sLen[m] - 1) {
                out[B_DIM * O_DIM + (size_t)b * H_DIM + ug] = h;                          // last_h
                out[B_DIM * O_DIM + (size_t)B_DIM * H_DIM + (size_t)b * H_DIM + ug] = c;  // last_c
            }
        }
        __syncthreads();                      // all h STG done CTA-wide

        // arrive on every cluster CTA's barrier (releases our g_h writes)
        if (tid < GC) mbar_arrive_rank(barAddr, (unsigned)tid);

        // tail work hidden under barrier skew: next step's embedding columns
        if (t + 1 < ctaMax) {
            #pragma unroll
            for (int rep = 0; rep < (BT * 32) / NTHR; ++rep) {
                int i4 = tid + rep * NTHR;
                int m = i4 >> 5, q = i4 & 31;
                float4 v = __ldg(reinterpret_cast<const float4*>(emb + (size_t)sTok[m] * E_DIM) + q);
                v.x = __uint_as_float(f2tf(v.x));
                v.y = __uint_as_float(f2tf(v.y));
                v.z = __uint_as_float(f2tf(v.z));
                v.w = __uint_as_float(f2tf(v.w));
                *reinterpret_cast<float4*>(&sA[m * ACT_ST + q * 4]) = v;
            }
        }
        __syncthreads();                      // prefill visible before next x-GEMM

        mbar_wait(barAddr, parity);           // all 16 CTAs arrived for step t
        parity ^= 1u;
    }

    // ---- decoder: decoded[b][o] = sigmoid(last_h[b] . dec_w[o]) ----
    if (gc == 0) {
        int pair = tid >> 2, part = tid & 3;   // 64 (b,o) pairs x 4-way split-k
        int m = pair >> 1, o = pair & 1;
        int b = b0 + m;
        const float* hrow = out + B_DIM * O_DIM + (size_t)b * H_DIM;
        const float* wrow = dec_w + o * H_DIM;
        float s = 0.f;
        #pragma unroll 16
        for (int u = part * 64; u < part * 64 + 64; ++u)
            s += __ldcg(hrow + u) * wrow[u];
        s += __shfl_xor_sync(0xffffffffu, s, 1);
        s += __shfl_xor_sync(0xffffffffu, s, 2);
        if (part == 0) out[b * O_DIM + o] = 1.0f / (1.0f + __expf(-s));
    }

    // clean cluster teardown
    asm volatile("barrier.cluster.arrive.aligned;" ::: "memory");
    asm volatile("barrier.cluster.wait.aligned;" ::: "memory");
}

extern "C" void kernel_launch(void* const* d_in, const int* in_sizes, int n_in,
                              void* d_out, int out_size) {
    const int*   inp = (const int*)d_in[0];
    const int*   len = (const int*)d_in[1];
    const float* h0  = (const float*)d_in[2];
    const float* c0  = (const float*)d_in[3];
    const float* emb = (const float*)d_in[4];
    const float* wih = (const float*)d_in[5];
    const float* whh = (const float*)d_in[6];
    const float* bih = (const float*)d_in[7];
    const float* bhh = (const float*)d_in[8];
    const float* dw  = (const float*)d_in[9];
    float* out = (float*)d_out;

    cudaFuncSetAttribute(lstm_kernel, cudaFuncAttributeMaxDynamicSharedMemorySize, SMEM_BYTES);
    cudaFuncSetAttribute(lstm_kernel, cudaFuncAttributeNonPortableClusterSizeAllowed, 1);
    lstm_kernel<<<NCTA, NTHR, SMEM_BYTES>>>(inp, len, h0, c0, emb, wih, whh, bih, bhh, dw, out);
}

// round 6
// speedup vs baseline: 1.4795x; 1.4795x over previous
#include <cuda_runtime.h>
#include <cstdint>

// Problem dims
#define S_LEN 1024
#define B_DIM 256
#define E_DIM 128
#define H_DIM 256
#define O_DIM 2
#define K_DIM (E_DIM + H_DIM)   // 384

// Decomposition: 8 batch groups x 16 hidden groups = 128 CTAs (1 per SM)
#define GB 8
#define GC 16
#define NCTA (GB * GC)
#define BT (B_DIM / GB)          // 32 batch rows per CTA
#define HS (H_DIM / GC)          // 16 hidden units per CTA
#define GT (4 * HS)              // 64 gate columns per CTA
#define NTHR 256

// GEMM warp layout: 4 k-split groups x 2 n-halves (fat warps: m32 x n32 each)
#define KS 4
#define NXT 4                    // x-part k-tiles per warp
#define NHT 8                    // h-part k-tiles per warp
#define NKT (NXT + NHT)          // 12

// SMEM strides (padded for bank-conflict-free mma fragment loads)
#define WT_ST 72
#define ACT_ST 388
#define G_ST 72

#define SMEM_F32 (K_DIM*WT_ST + BT*ACT_ST + KS*BT*G_ST + BT*HS + GT + BT + BT + 4)
#define SMEM_BYTES (SMEM_F32 * 4)
static_assert(SMEM_BYTES <= 227 * 1024, "smem too big");

// Global scratch: double-buffered hidden state (tf32-rounded fp32 bits)
__device__ float g_h[2][B_DIM][H_DIM];
// Per-group barrier: cnt / gen on separate 128B lines per group.
// cnt is always 0 at kernel entry (last releaser resets it each use).
// gen is MONOTONIC across uses and graph replays; CTAs sample it at entry.
__device__ unsigned g_cnt[GB][32];
__device__ unsigned g_gen[GB][32];

__device__ __forceinline__ unsigned f2tf(float x) {
    unsigned u; asm("cvt.rna.tf32.f32 %0, %1;" : "=r"(u) : "f"(x)); return u;
}
__device__ __forceinline__ float sigf(float x) {
    return __fdividef(1.0f, 1.0f + __expf(-x));
}
__device__ __forceinline__ float tanhfast(float x) {
    return 2.0f * __fdividef(1.0f, 1.0f + __expf(-2.0f * x)) - 1.0f;
}

__device__ __forceinline__ void mma8(float& d0, float& d1, float& d2, float& d3,
                                     unsigned a0, unsigned a1, unsigned a2, unsigned a3,
                                     unsigned b0, unsigned b1) {
    asm volatile(
        "mma.sync.aligned.m16n8k8.row.col.f32.tf32.tf32.f32 "
        "{%0,%1,%2,%3},{%4,%5,%6,%7},{%8,%9},{%0,%1,%2,%3};"
        : "+f"(d0), "+f"(d1), "+f"(d2), "+f"(d3)
        : "r"(a0), "r"(a1), "r"(a2), "r"(a3), "r"(b0), "r"(b1));
}

#define CP_ASYNC16(dst_u32, src) \
    asm volatile("cp.async.cg.shared.global [%0], [%1], 16;" :: "r"(dst_u32), "l"(src))
#define CP_COMMIT() asm volatile("cp.async.commit_group;")
#define CP_WAIT0()  asm volatile("cp.async.wait_group 0;")

// Arrive (tid0 only): release our writes, count in; last arriver resets cnt
// and publishes the new generation (absolute value `target`).
__device__ __forceinline__ void gbar_arrive(int gb, unsigned target) {
    unsigned* cnt = &g_cnt[gb][0];
    unsigned* gen = &g_gen[gb][0];
    unsigned old;
    asm volatile("atom.acq_rel.gpu.global.add.u32 %0, [%1], %2;"
                 : "=r"(old) : "l"(cnt), "r"(1u) : "memory");
    if (old == GC - 1u) {
        asm volatile("st.relaxed.gpu.global.u32 [%0], %1;" :: "l"(cnt), "r"(0u) : "memory");
        asm volatile("st.release.gpu.global.u32 [%0], %1;" :: "l"(gen), "r"(target) : "memory");
    }
}
// Wait (tid0 only): spin until generation reaches `target`.
__device__ __forceinline__ void gbar_wait(int gb, unsigned target) {
    unsigned* gen = &g_gen[gb][0];
    unsigned v;
    do {
        asm volatile("ld.acquire.gpu.global.u32 %0, [%1];" : "=r"(v) : "l"(gen) : "memory");
    } while ((int)(v - target) < 0);
}

__global__ void __launch_bounds__(NTHR, 1)
lstm_kernel(const int* __restrict__ inp, const int* __restrict__ lengths,
            const float* __restrict__ h0, const float* __restrict__ c0,
            const float* __restrict__ emb, const float* __restrict__ w_ih,
            const float* __restrict__ w_hh, const float* __restrict__ b_ih,
            const float* __restrict__ b_hh, const float* __restrict__ dec_w,
            float* __restrict__ out) {
    extern __shared__ float sm[];
    float* sW    = sm;                         // [K_DIM][WT_ST]
    float* sA    = sW + K_DIM * WT_ST;         // [BT][ACT_ST]
    float* sG    = sA + BT * ACT_ST;           // [KS][BT][G_ST] gate partials
    float* sC    = sG + KS * BT * G_ST;        // [BT][HS]
    float* sBias = sC + BT * HS;               // [GT]
    int*   sLen  = (int*)(sBias + GT);         // [BT]
    int*   sTok  = sLen + BT;                  // [BT]
    int*   sMax  = sTok + BT;                  // [1]

    const int tid = threadIdx.x;
    const int cta = blockIdx.x;
    const int gb = cta / GC;
    const int gc = cta % GC;
    const int b0 = gb * BT;

    // Sample the generation counter BEFORE our first arrive (race-free: gen
    // cannot advance until this CTA arrives). Only tid0 uses it.
    unsigned gen0 = 0;
    if (tid == 0) {
        asm volatile("ld.acquire.gpu.global.u32 %0, [%1];"
                     : "=r"(gen0) : "l"(&g_gen[gb][0]) : "memory");
    }

    // ---- one-time init: weights (tf32), bias, lengths, c state, h[0] ----
    for (int idx = tid; idx < K_DIM * GT; idx += NTHR) {
        int k = idx / GT, c = idx % GT;
        int grow = (c / HS) * H_DIM + gc * HS + (c % HS);   // gate order i,f,g,o
        float w = (k < E_DIM) ? w_ih[grow * E_DIM + k] : w_hh[grow * H_DIM + (k - E_DIM)];
        sW[k * WT_ST + c] = __uint_as_float(f2tf(w));
    }
    if (tid < GT) {
        int grow = (tid / HS) * H_DIM + gc * HS + (tid % HS);
        sBias[tid] = b_ih[grow] + b_hh[grow];
    }
    if (tid < BT) sLen[tid] = lengths[b0 + tid];
    for (int idx = tid; idx < BT * HS; idx += NTHR) {
        int m = idx / HS, u = idx % HS;
        sC[idx] = c0[(b0 + m) * H_DIM + gc * HS + u];
    }
    if (gc == 0) {
        for (int idx = tid; idx < BT * H_DIM; idx += NTHR) {
            int m = idx / H_DIM, u = idx % H_DIM;
            g_h[0][b0 + m][u] = __uint_as_float(f2tf(h0[(b0 + m) * H_DIM + u]));
        }
    }
    if (tid < BT) sTok[tid] = inp[b0 + tid];   // tokens for t = 0
    __syncthreads();
    if (tid == 0) {
        int mx = 0;
        for (int i = 0; i < BT; ++i) mx = max(mx, sLen[i]);
        sMax[0] = mx;
    }
    __syncthreads();
    const int ctaMax = sMax[0];                // uniform across the group (same rows)

    const int lane = tid & 31, warp = tid >> 5;
    const int ng = warp & 1;      // n half: 32 cols
    const int ks = warp >> 1;     // k slice

    // ---- preload this warp's B fragments into registers (step-invariant) ----
    unsigned bw[NKT][4][2];
    #pragma unroll
    for (int i = 0; i < NKT; ++i) {
        int ktg = (i < NXT) ? (ks * NXT + i) : (16 + ks * NHT + (i - NXT));
        const float* Bk = &sW[(ktg * 8 + (lane & 3)) * WT_ST + ng * 32 + (lane >> 2)];
        #pragma unroll
        for (int j = 0; j < 4; ++j) {
            bw[i][j][0] = __float_as_uint(Bk[j * 8]);
            bw[i][j][1] = __float_as_uint(Bk[4 * WT_ST + j * 8]);
        }
    }

    // prologue: embedding columns of sA for t = 0
    #pragma unroll
    for (int rep = 0; rep < (BT * 32) / NTHR; ++rep) {
        int i4 = tid + rep * NTHR;
        int m = i4 >> 5, q = i4 & 31;
        float4 v = __ldg(reinterpret_cast<const float4*>(emb + (size_t)sTok[m] * E_DIM) + q);
        v.x = __uint_as_float(f2tf(v.x));
        v.y = __uint_as_float(f2tf(v.y));
        v.z = __uint_as_float(f2tf(v.z));
        v.w = __uint_as_float(f2tf(v.w));
        *reinterpret_cast<float4*>(&sA[m * ACT_ST + q * 4]) = v;
    }
    // barrier use #1: g_h[0] + init visible group-wide
    __syncthreads();
    if (tid == 0) {
        gbar_arrive(gb, gen0 + 1u);
        gbar_wait(gb, gen0 + 1u);
    }
    __syncthreads();

    // ---- recurrence (group-local; early exit at group max length) ----
    for (int t = 0; t < ctaMax; ++t) {
        const int cur = t & 1, nxt = cur ^ 1;

        // phase 1a: issue async h[t] gather into sA cols 128..383 (no reg landing)
        #pragma unroll
        for (int rep = 0; rep < (BT * 64) / NTHR; ++rep) {
            int i4 = tid + rep * NTHR;
            int m = i4 >> 6, q = i4 & 63;
            unsigned dst = (unsigned)__cvta_generic_to_shared(&sA[m * ACT_ST + 128 + q * 4]);
            CP_ASYNC16(dst, &g_h[cur][b0 + m][q * 4]);
        }
        CP_COMMIT();
        // prefetch next tokens (independent)
        if (tid < BT && t + 1 < ctaMax) sTok[tid] = inp[(t + 1) * B_DIM + b0 + tid];

        // phase 1b: x-part GEMM (emb columns prefetched last step) while gather flies
        float acc[2][4][4] = {};
        const float* Ab = &sA[(lane >> 2) * ACT_ST + (lane & 3)];
        #pragma unroll
        for (int i = 0; i < NXT; ++i) {
            const int kk = (ks * NXT + i) * 8;
            unsigned a[2][4];
            #pragma unroll
            for (int mg = 0; mg < 2; ++mg) {
                const float* Ak = Ab + mg * 16 * ACT_ST + kk;
                a[mg][0] = __float_as_uint(Ak[0]);
                a[mg][1] = __float_as_uint(Ak[8 * ACT_ST]);
                a[mg][2] = __float_as_uint(Ak[4]);
                a[mg][3] = __float_as_uint(Ak[8 * ACT_ST + 4]);
            }
            #pragma unroll
            for (int j = 0; j < 4; ++j) {
                mma8(acc[0][j][0], acc[0][j][1], acc[0][j][2], acc[0][j][3],
                     a[0][0], a[0][1], a[0][2], a[0][3], bw[i][j][0], bw[i][j][1]);
                mma8(acc[1][j][0], acc[1][j][1], acc[1][j][2], acc[1][j][3],
                     a[1][0], a[1][1], a[1][2], a[1][3], bw[i][j][0], bw[i][j][1]);
            }
        }
        CP_WAIT0();
        __syncthreads();

        // phase 2: h-part GEMM (k = 128..383)
        #pragma unroll
        for (int i = 0; i < NHT; ++i) {
            const int kk = (16 + ks * NHT + i) * 8;
            unsigned a[2][4];
            #pragma unroll
            for (int mg = 0; mg < 2; ++mg) {
                const float* Ak = Ab + mg * 16 * ACT_ST + kk;
                a[mg][0] = __float_as_uint(Ak[0]);
                a[mg][1] = __float_as_uint(Ak[8 * ACT_ST]);
                a[mg][2] = __float_as_uint(Ak[4]);
                a[mg][3] = __float_as_uint(Ak[8 * ACT_ST + 4]);
            }
            #pragma unroll
            for (int j = 0; j < 4; ++j) {
                mma8(acc[0][j][0], acc[0][j][1], acc[0][j][2], acc[0][j][3],
                     a[0][0], a[0][1], a[0][2], a[0][3], bw[NXT + i][j][0], bw[NXT + i][j][1]);
                mma8(acc[1][j][0], acc[1][j][1], acc[1][j][2], acc[1][j][3],
                     a[1][0], a[1][1], a[1][2], a[1][3], bw[NXT + i][j][0], bw[NXT + i][j][1]);
            }
        }
        {   // spill gate partial tile to smem
            float* sGp = sG + ks * BT * G_ST;
            #pragma unroll
            for (int mg = 0; mg < 2; ++mg) {
                int r = mg * 16 + (lane >> 2);
                #pragma unroll
                for (int j = 0; j < 4; ++j) {
                    int cb = ng * 32 + j * 8 + 2 * (lane & 3);
                    sGp[r * G_ST + cb]           = acc[mg][j][0];
                    sGp[r * G_ST + cb + 1]       = acc[mg][j][1];
                    sGp[(r + 8) * G_ST + cb]     = acc[mg][j][2];
                    sGp[(r + 8) * G_ST + cb + 1] = acc[mg][j][3];
                }
            }
        }
        __syncthreads();

        // phase 3: elementwise cell update (+ partial-sum combine)
        #pragma unroll
        for (int rep = 0; rep < (BT * HS) / NTHR; ++rep) {
            int idx = tid + rep * NTHR;
            int m = idx >> 4, u = idx & 15;
            float xi = sBias[u], xf = sBias[HS + u], xg = sBias[2 * HS + u], xo = sBias[3 * HS + u];
            #pragma unroll
            for (int p = 0; p < KS; ++p) {
                const float* gm = &sG[p * BT * G_ST + m * G_ST];
                xi += gm[u];
                xf += gm[HS + u];
                xg += gm[2 * HS + u];
                xo += gm[3 * HS + u];
            }
            float ii = sigf(xi), ff = sigf(xf), gg = tanhfast(xg), oo = sigf(xo);
            float c = ff * sC[idx] + ii * gg;
            sC[idx] = c;
            float h = oo * tanhfast(c);
            int b = b0 + m, ug = gc * HS + u;
            g_h[nxt][b][ug] = __uint_as_float(f2tf(h));
            if (t == sLen[m] - 1) {
                out[B_DIM * O_DIM + (size_t)b * H_DIM + ug] = h;                          // last_h
                out[B_DIM * O_DIM + (size_t)B_DIM * H_DIM + (size_t)b * H_DIM + ug] = c;  // last_c
            }
        }
        __syncthreads();                      // all h STG issued CTA-wide

        // barrier ARRIVE first (releases our g_h writes to the group) ...
        if (tid == 0) gbar_arrive(gb, gen0 + 2u + (unsigned)t);

        // ... then hide next step's embedding prefill under the barrier skew
        if (t + 1 < ctaMax) {
            #pragma unroll
            for (int rep = 0; rep < (BT * 32) / NTHR; ++rep) {
                int i4 = tid + rep * NTHR;
                int m = i4 >> 5, q = i4 & 31;
                float4 v = __ldg(reinterpret_cast<const float4*>(emb + (size_t)sTok[m] * E_DIM) + q);
                v.x = __uint_as_float(f2tf(v.x));
                v.y = __uint_as_float(f2tf(v.y));
                v.z = __uint_as_float(f2tf(v.z));
                v.w = __uint_as_float(f2tf(v.w));
                *reinterpret_cast<float4*>(&sA[m * ACT_ST + q * 4]) = v;
            }
        }

        // ... and only now WAIT for the group
        if (tid == 0) gbar_wait(gb, gen0 + 2u + (unsigned)t);
        __syncthreads();
    }

    // ---- decoder: decoded[b][o] = sigmoid(last_h[b] . dec_w[o]) ----
    if (gc == 0) {
        int pair = tid >> 2, part = tid & 3;   // 64 (b,o) pairs x 4-way split-k
        int m = pair >> 1, o = pair & 1;
        int b = b0 + m;
        const float* hrow = out + B_DIM * O_DIM + (size_t)b * H_DIM;
        const float* wrow = dec_w + o * H_DIM;
        float s = 0.f;
        #pragma unroll 16
        for (int u = part * 64; u < part * 64 + 64; ++u)
            s += __ldcg(hrow + u) * wrow[u];
        s += __shfl_xor_sync(0xffffffffu, s, 1);
        s += __shfl_xor_sync(0xffffffffu, s, 2);
        if (part == 0) out[b * O_DIM + o] = 1.0f / (1.0f + __expf(-s));
    }
}

extern "C" void kernel_launch(void* const* d_in, const int* in_sizes, int n_in,
                              void* d_out, int out_size) {
    const int*   inp = (const int*)d_in[0];
    const int*   len = (const int*)d_in[1];
    const float* h0  = (const float*)d_in[2];
    const float* c0  = (const float*)d_in[3];
    const float* emb = (const float*)d_in[4];
    const float* wih = (const float*)d_in[5];
    const float* whh = (const float*)d_in[6];
    const float* bih = (const float*)d_in[7];
    const float* bhh = (const float*)d_in[8];
    const float* dw  = (const float*)d_in[9];
    float* out = (float*)d_out;

    cudaFuncSetAttribute(lstm_kernel, cudaFuncAttributeMaxDynamicSharedMemorySize, SMEM_BYTES);
    lstm_kernel<<<NCTA, NTHR, SMEM_BYTES>>>(inp, len, h0, c0, emb, wih, whh, bih, bhh, dw, out);
}

// round 7
// speedup vs baseline: 1.9300x; 1.3045x over previous
#include <cuda_runtime.h>
#include <cstdint>

// Problem dims
#define S_LEN 1024
#define B_DIM 256
#define E_DIM 128
#define H_DIM 256
#define O_DIM 2
#define K_DIM (E_DIM + H_DIM)   // 384

// Decomposition: 8 batch groups x 16 hidden groups = 128 CTAs (1 per SM)
#define GB 8
#define GC 16
#define NCTA (GB * GC)
#define BT (B_DIM / GB)          // 32 batch rows per CTA
#define HS (H_DIM / GC)          // 16 hidden units per CTA
#define GT (4 * HS)              // 64 gate columns per CTA
#define NTHR 256

// GEMM warp layout: 4 k-split groups x 2 n-halves (fat warps: m32 x n32 each)
#define KS 4
#define NXT 4                    // x-part k-tiles per warp
#define NHT 8                    // h-part k-tiles per warp
#define NKT (NXT + NHT)          // 12

// Hidden-state ring depth (producer/consumer slack)
#define HD 4

// SMEM strides (padded for bank-conflict-free mma fragment loads)
#define WT_ST 72
#define ACT_ST 388
#define G_ST 72

#define SMEM_F32 (K_DIM*WT_ST + BT*ACT_ST + KS*BT*G_ST + BT*HS + GT + BT + BT + 4 + 32)
#define SMEM_BYTES (SMEM_F32 * 4)
static_assert(SMEM_BYTES <= 227 * 1024, "smem too big");

// Global scratch: ring-buffered hidden state (tf32-rounded fp32 bits)
__device__ float g_h[HD][B_DIM][H_DIM];
// Init/final barrier (monotonic gen, replay-safe)
__device__ unsigned g_cnt[GB][32];
__device__ unsigned g_gen[GB][32];
// Dataflow flags: monotonic, one 128B line each. ready[gc]=base+k <=> h_k published.
// cons[gc]=base+k <=> steps 0..k-1 gathered by that CTA.
__device__ unsigned g_ready[GB][GC][32];
__device__ unsigned g_cons[GB][GC][32];

__device__ __forceinline__ unsigned f2tf(float x) {
    unsigned u; asm("cvt.rna.tf32.f32 %0, %1;" : "=r"(u) : "f"(x)); return u;
}
__device__ __forceinline__ float sigf(float x) {
    return __fdividef(1.0f, 1.0f + __expf(-x));
}
__device__ __forceinline__ float tanhfast(float x) {
    return 2.0f * __fdividef(1.0f, 1.0f + __expf(-2.0f * x)) - 1.0f;
}

__device__ __forceinline__ void mma8(float& d0, float& d1, float& d2, float& d3,
                                     unsigned a0, unsigned a1, unsigned a2, unsigned a3,
                                     unsigned b0, unsigned b1) {
    asm volatile(
        "mma.sync.aligned.m16n8k8.row.col.f32.tf32.tf32.f32 "
        "{%0,%1,%2,%3},{%4,%5,%6,%7},{%8,%9},{%0,%1,%2,%3};"
        : "+f"(d0), "+f"(d1), "+f"(d2), "+f"(d3)
        : "r"(a0), "r"(a1), "r"(a2), "r"(a3), "r"(b0), "r"(b1));
}

#define CP_ASYNC16(dst_u32, src) \
    asm volatile("cp.async.cg.shared.global [%0], [%1], 16;" :: "r"(dst_u32), "l"(src))
#define CP_COMMIT() asm volatile("cp.async.commit_group;")
#define CP_WAIT0()  asm volatile("cp.async.wait_group 0;")

__device__ __forceinline__ unsigned ld_acq(const unsigned* p) {
    unsigned v;
    asm volatile("ld.acquire.gpu.global.u32 %0, [%1];" : "=r"(v) : "l"(p) : "memory");
    return v;
}
__device__ __forceinline__ void st_rel(unsigned* p, unsigned v) {
    asm volatile("st.release.gpu.global.u32 [%0], %1;" :: "l"(p), "r"(v) : "memory");
}

// Init/final barrier (tid0 only): arrive then wait for absolute generation.
__device__ __forceinline__ void gbar_arrive(int gb, unsigned target) {
    unsigned old;
    asm volatile("atom.acq_rel.gpu.global.add.u32 %0, [%1], %2;"
                 : "=r"(old) : "l"(&g_cnt[gb][0]), "r"(1u) : "memory");
    if (old == GC - 1u) {
        asm volatile("st.relaxed.gpu.global.u32 [%0], %1;" :: "l"(&g_cnt[gb][0]), "r"(0u) : "memory");
        st_rel(&g_gen[gb][0], target);
    }
}
__device__ __forceinline__ void gbar_wait(int gb, unsigned target) {
    while ((int)(ld_acq(&g_gen[gb][0]) - target) < 0) {}
}

__global__ void __launch_bounds__(NTHR, 1)
lstm_kernel(const int* __restrict__ inp, const int* __restrict__ lengths,
            const float* __restrict__ h0, const float* __restrict__ c0,
            const float* __restrict__ emb, const float* __restrict__ w_ih,
            const float* __restrict__ w_hh, const float* __restrict__ b_ih,
            const float* __restrict__ b_hh, const float* __restrict__ dec_w,
            float* __restrict__ out) {
    extern __shared__ float sm[];
    float* sW    = sm;                         // [K_DIM][WT_ST]
    float* sA    = sW + K_DIM * WT_ST;         // [BT][ACT_ST]
    float* sG    = sA + BT * ACT_ST;           // [KS][BT][G_ST] gate partials
    float* sC    = sG + KS * BT * G_ST;        // [BT][HS]
    float* sBias = sC + BT * HS;               // [GT]
    int*   sLen  = (int*)(sBias + GT);         // [BT]
    int*   sTok  = sLen + BT;                  // [BT]
    int*   sMax  = sTok + BT;                  // [1]
    unsigned* sRdyBase  = (unsigned*)(sMax + 4);   // [16]
    unsigned* sConsBase = sRdyBase + 16;           // [16]

    const int tid = threadIdx.x;
    const int cta = blockIdx.x;
    const int gb = cta / GC;
    const int gc = cta % GC;
    const int b0 = gb * BT;

    // --- entry sampling (race-free: nobody writes these until after init barrier,
    //     and nobody reaches the init barrier release before we arrive) ---
    unsigned gen0 = 0;
    if (tid == 0) gen0 = ld_acq(&g_gen[gb][0]);
    if (tid < GC) {
        sRdyBase[tid]  = ld_acq(&g_ready[gb][tid][0]);
        sConsBase[tid] = ld_acq(&g_cons[gb][tid][0]);
    }

    // ---- one-time init: weights (tf32), bias, lengths, c state, h[0] ----
    for (int idx = tid; idx < K_DIM * GT; idx += NTHR) {
        int k = idx / GT, c = idx % GT;
        int grow = (c / HS) * H_DIM + gc * HS + (c % HS);   // gate order i,f,g,o
        float w = (k < E_DIM) ? w_ih[grow * E_DIM + k] : w_hh[grow * H_DIM + (k - E_DIM)];
        sW[k * WT_ST + c] = __uint_as_float(f2tf(w));
    }
    if (tid < GT) {
        int grow = (tid / HS) * H_DIM + gc * HS + (tid % HS);
        sBias[tid] = b_ih[grow] + b_hh[grow];
    }
    if (tid < BT) sLen[tid] = lengths[b0 + tid];
    for (int idx = tid; idx < BT * HS; idx += NTHR) {
        int m = idx / HS, u = idx % HS;
        sC[idx] = c0[(b0 + m) * H_DIM + gc * HS + u];
    }
    if (gc == 0) {
        for (int idx = tid; idx < BT * H_DIM; idx += NTHR) {
            int m = idx / H_DIM, u = idx % H_DIM;
            g_h[0][b0 + m][u] = __uint_as_float(f2tf(h0[(b0 + m) * H_DIM + u]));
        }
    }
    if (tid < BT) sTok[tid] = inp[b0 + tid];   // tokens for t = 0
    __syncthreads();
    if (tid == 0) {
        int mx = 0;
        for (int i = 0; i < BT; ++i) mx = max(mx, sLen[i]);
        sMax[0] = mx;
    }
    __syncthreads();
    const int ctaMax = sMax[0];                // uniform across the group (same rows)
    const unsigned rdyOwn  = sRdyBase[gc];
    const unsigned consOwn = sConsBase[gc];

    const int lane = tid & 31, warp = tid >> 5;
    const int ng = warp & 1;      // n half: 32 cols
    const int ks = warp >> 1;     // k slice

    // ---- preload this warp's B fragments into registers (step-invariant) ----
    unsigned bw[NKT][4][2];
    #pragma unroll
    for (int i = 0; i < NKT; ++i) {
        int ktg = (i < NXT) ? (ks * NXT + i) : (16 + ks * NHT + (i - NXT));
        const float* Bk = &sW[(ktg * 8 + (lane & 3)) * WT_ST + ng * 32 + (lane >> 2)];
        #pragma unroll
        for (int j = 0; j < 4; ++j) {
            bw[i][j][0] = __float_as_uint(Bk[j * 8]);
            bw[i][j][1] = __float_as_uint(Bk[4 * WT_ST + j * 8]);
        }
    }

    // prologue: embedding columns of sA for t = 0
    #pragma unroll
    for (int rep = 0; rep < (BT * 32) / NTHR; ++rep) {
        int i4 = tid + rep * NTHR;
        int m = i4 >> 5, q = i4 & 31;
        float4 v = __ldg(reinterpret_cast<const float4*>(emb + (size_t)sTok[m] * E_DIM) + q);
        v.x = __uint_as_float(f2tf(v.x));
        v.y = __uint_as_float(f2tf(v.y));
        v.z = __uint_as_float(f2tf(v.z));
        v.w = __uint_as_float(f2tf(v.w));
        *reinterpret_cast<float4*>(&sA[m * ACT_ST + q * 4]) = v;
    }
    // init barrier: h_0 + init visible group-wide (also orders flag sampling)
    __syncthreads();
    if (tid == 0) {
        gbar_arrive(gb, gen0 + 1u);
        gbar_wait(gb, gen0 + 1u);
    }
    __syncthreads();

    // ---- recurrence: producer/consumer dataflow, no per-step barrier ----
    for (int t = 0; t < ctaMax; ++t) {
        const int rd = t & (HD - 1);           // slot holding h_t
        const int wr = (t + 1) & (HD - 1);     // slot receiving h_{t+1}

        // phase 1a: issue async h_t gather into sA cols 128..383
        #pragma unroll
        for (int rep = 0; rep < (BT * 64) / NTHR; ++rep) {
            int i4 = tid + rep * NTHR;
            int m = i4 >> 6, q = i4 & 63;
            unsigned dst = (unsigned)__cvta_generic_to_shared(&sA[m * ACT_ST + 128 + q * 4]);
            CP_ASYNC16(dst, &g_h[rd][b0 + m][q * 4]);
        }
        CP_COMMIT();
        // prefetch next tokens (independent)
        if (tid < BT && t + 1 < ctaMax) sTok[tid] = inp[(t + 1) * B_DIM + b0 + tid];

        // phase 1b: x-part GEMM (emb columns prefetched last step) while gather flies
        float acc[2][4][4] = {};
        const float* Ab = &sA[(lane >> 2) * ACT_ST + (lane & 3)];
        #pragma unroll
        for (int i = 0; i < NXT; ++i) {
            const int kk = (ks * NXT + i) * 8;
            unsigned a[2][4];
            #pragma unroll
            for (int mg = 0; mg < 2; ++mg) {
                const float* Ak = Ab + mg * 16 * ACT_ST + kk;
                a[mg][0] = __float_as_uint(Ak[0]);
                a[mg][1] = __float_as_uint(Ak[8 * ACT_ST]);
                a[mg][2] = __float_as_uint(Ak[4]);
                a[mg][3] = __float_as_uint(Ak[8 * ACT_ST + 4]);
            }
            #pragma unroll
            for (int j = 0; j < 4; ++j) {
                mma8(acc[0][j][0], acc[0][j][1], acc[0][j][2], acc[0][j][3],
                     a[0][0], a[0][1], a[0][2], a[0][3], bw[i][j][0], bw[i][j][1]);
                mma8(acc[1][j][0], acc[1][j][1], acc[1][j][2], acc[1][j][3],
                     a[1][0], a[1][1], a[1][2], a[1][3], bw[i][j][0], bw[i][j][1]);
            }
        }
        CP_WAIT0();
        __syncthreads();
        // our gather of step t is complete -> release the slot for producers
        if (tid == 0) st_rel(&g_cons[gb][gc][0], consOwn + (unsigned)t + 1u);

        // phase 2: h-part GEMM (k = 128..383)
        #pragma unroll
        for (int i = 0; i < NHT; ++i) {
            const int kk = (16 + ks * NHT + i) * 8;
            unsigned a[2][4];
            #pragma unroll
            for (int mg = 0; mg < 2; ++mg) {
                const float* Ak = Ab + mg * 16 * ACT_ST + kk;
                a[mg][0] = __float_as_uint(Ak[0]);
                a[mg][1] = __float_as_uint(Ak[8 * ACT_ST]);
                a[mg][2] = __float_as_uint(Ak[4]);
                a[mg][3] = __float_as_uint(Ak[8 * ACT_ST + 4]);
            }
            #pragma unroll
            for (int j = 0; j < 4; ++j) {
                mma8(acc[0][j][0], acc[0][j][1], acc[0][j][2], acc[0][j][3],
                     a[0][0], a[0][1], a[0][2], a[0][3], bw[NXT + i][j][0], bw[NXT + i][j][1]);
                mma8(acc[1][j][0], acc[1][j][1], acc[1][j][2], acc[1][j][3],
                     a[1][0], a[1][1], a[1][2], a[1][3], bw[NXT + i][j][0], bw[NXT + i][j][1]);
            }
        }
        {   // spill gate partial tile to smem
            float* sGp = sG + ks * BT * G_ST;
            #pragma unroll
            for (int mg = 0; mg < 2; ++mg) {
                int r = mg * 16 + (lane >> 2);
                #pragma unroll
                for (int j = 0; j < 4; ++j) {
                    int cb = ng * 32 + j * 8 + 2 * (lane & 3);
                    sGp[r * G_ST + cb]           = acc[mg][j][0];
                    sGp[r * G_ST + cb + 1]       = acc[mg][j][1];
                    sGp[(r + 8) * G_ST + cb]     = acc[mg][j][2];
                    sGp[(r + 8) * G_ST + cb + 1] = acc[mg][j][3];
                }
            }
        }
        __syncthreads();

        // phase 3: elementwise cell update (writes h_{t+1} into ring slot wr).
        // Slot-free guarantee: all consumers gathered step t+1-HD (checked at
        // tail of step t-1; trivially true for t < HD-1).
        #pragma unroll
        for (int rep = 0; rep < (BT * HS) / NTHR; ++rep) {
            int idx = tid + rep * NTHR;
            int m = idx >> 4, u = idx & 15;
            float xi = sBias[u], xf = sBias[HS + u], xg = sBias[2 * HS + u], xo = sBias[3 * HS + u];
            #pragma unroll
            for (int p = 0; p < KS; ++p) {
                const float* gm = &sG[p * BT * G_ST + m * G_ST];
                xi += gm[u];
                xf += gm[HS + u];
                xg += gm[2 * HS + u];
                xo += gm[3 * HS + u];
            }
            float ii = sigf(xi), ff = sigf(xf), gg = tanhfast(xg), oo = sigf(xo);
            float c = ff * sC[idx] + ii * gg;
            sC[idx] = c;
            float h = oo * tanhfast(c);
            int b = b0 + m, ug = gc * HS + u;
            g_h[wr][b][ug] = __uint_as_float(f2tf(h));
            if (t == sLen[m] - 1) {
                out[B_DIM * O_DIM + (size_t)b * H_DIM + ug] = h;                          // last_h
                out[B_DIM * O_DIM + (size_t)B_DIM * H_DIM + (size_t)b * H_DIM + ug] = c;  // last_c
            }
        }
        __syncthreads();                      // all h STG issued CTA-wide
        // publish h_{t+1}
        if (tid == 0) st_rel(&g_ready[gb][gc][0], rdyOwn + (unsigned)t + 1u);

        // tail: warp 0 polls flags for step t+1; warps 1-7 prefill next embeddings
        if (t + 1 < ctaMax) {
            if (warp == 0) {
                // lanes 0-15: ready[h_{t+1}] ; lanes 16-31: cons for slot (t+2)%HD
                unsigned i = lane & 15;
                const unsigned* ptr = (lane < 16) ? &g_ready[gb][i][0] : &g_cons[gb][i][0];
                int dcons = t + 3 - HD; if (dcons < 0) dcons = 0;
                unsigned tgt = (lane < 16) ? (sRdyBase[i] + (unsigned)(t + 1))
                                           : (sConsBase[i] + (unsigned)dcons);
                bool ok = false;
                do {
                    if (!ok) ok = ((int)(ld_acq(ptr) - tgt) >= 0);
                } while (!__all_sync(0xffffffffu, ok));
            } else {
                for (int i4 = tid - 32; i4 < BT * 32; i4 += NTHR - 32) {
                    int m = i4 >> 5, q = i4 & 31;
                    float4 v = __ldg(reinterpret_cast<const float4*>(emb + (size_t)sTok[m] * E_DIM) + q);
                    v.x = __uint_as_float(f2tf(v.x));
                    v.y = __uint_as_float(f2tf(v.y));
                    v.z = __uint_as_float(f2tf(v.z));
                    v.w = __uint_as_float(f2tf(v.w));
                    *reinterpret_cast<float4*>(&sA[m * ACT_ST + q * 4]) = v;
                }
            }
        }
        __syncthreads();                      // polls + prefill visible block-wide
    }

    // final join: all snapshots visible before the decoder
    if (tid == 0) {
        gbar_arrive(gb, gen0 + 2u);
        gbar_wait(gb, gen0 + 2u);
    }
    __syncthreads();

    // ---- decoder: decoded[b][o] = sigmoid(last_h[b] . dec_w[o]) ----
    if (gc == 0) {
        int pair = tid >> 2, part = tid & 3;   // 64 (b,o) pairs x 4-way split-k
        int m = pair >> 1, o = pair & 1;
        int b = b0 + m;
        const float* hrow = out + B_DIM * O_DIM + (size_t)b * H_DIM;
        const float* wrow = dec_w + o * H_DIM;
        float s = 0.f;
        #pragma unroll 16
        for (int u = part * 64; u < part * 64 + 64; ++u)
            s += __ldcg(hrow + u) * wrow[u];
        s += __shfl_xor_sync(0xffffffffu, s, 1);
        s += __shfl_xor_sync(0xffffffffu, s, 2);
        if (part == 0) out[b * O_DIM + o] = 1.0f / (1.0f + __expf(-s));
    }
}

extern "C" void kernel_launch(void* const* d_in, const int* in_sizes, int n_in,
                              void* d_out, int out_size) {
    const int*   inp = (const int*)d_in[0];
    const int*   len = (const int*)d_in[1];
    const float* h0  = (const float*)d_in[2];
    const float* c0  = (const float*)d_in[3];
    const float* emb = (const float*)d_in[4];
    const float* wih = (const float*)d_in[5];
    const float* whh = (const float*)d_in[6];
    const float* bih = (const float*)d_in[7];
    const float* bhh = (const float*)d_in[8];
    const float* dw  = (const float*)d_in[9];
    float* out = (float*)d_out;

    cudaFuncSetAttribute(lstm_kernel, cudaFuncAttributeMaxDynamicSharedMemorySize, SMEM_BYTES);
    lstm_kernel<<<NCTA, NTHR, SMEM_BYTES>>>(inp, len, h0, c0, emb, wih, whh, bih, bhh, dw, out);
}

// round 8
// speedup vs baseline: 2.2573x; 1.1696x over previous
#include <cuda_runtime.h>
#include <cuda_fp16.h>
#include <cstdint>

// Problem dims
#define S_LEN 1024
#define B_DIM 256
#define E_DIM 128
#define H_DIM 256
#define O_DIM 2
#define K_DIM (E_DIM + H_DIM)   // 384

// Decomposition: 8 batch groups x 16 hidden groups = 128 CTAs (1 per SM)
#define GB 8
#define GC 16
#define NCTA (GB * GC)
#define BT (B_DIM / GB)          // 32 batch rows per CTA
#define HS (H_DIM / GC)          // 16 hidden units per CTA
#define GT (4 * HS)              // 64 gate columns per CTA
#define NTHR 256

// fp16 GEMM: k16 tiles. 24 total; warp layout 4 k-split x 2 n-halves.
#define KS 4
#define NXT2 2                   // x-part k16-tiles per warp (8 total / 4)
#define NHT2 4                   // h-part k16-tiles per warp (16 total / 4)
#define NKT2 (NXT2 + NHT2)       // 6

// Hidden-state ring depth (producer/consumer slack)
#define HD 4

// Strides
#define WT_ST 72                 // f32 weight [k][col] (init only)
#define ACT_STH 392              // sA row stride in halves (392/2 mod 32 == 4 -> 2-wf LDS.64)
#define ACT_STB (ACT_STH * 2)    // 784 bytes
#define G_ST 72                  // f32 gate partials

// SMEM byte layout
#define OFF_W    0
#define OFF_A    (OFF_W + K_DIM * WT_ST * 4)          // 110592
#define OFF_G    (OFF_A + BT * ACT_STB)               // +25088
#define OFF_C    (OFF_G + KS * BT * G_ST * 4)         // +36864
#define OFF_BIAS (OFF_C + BT * HS * 4)
#define OFF_LEN  (OFF_BIAS + GT * 4)
#define OFF_TOK  (OFF_LEN + BT * 4)
#define OFF_MAX  (OFF_TOK + BT * 4)
#define OFF_RDY  (OFF_MAX + 16)
#define OFF_CONS (OFF_RDY + 64)
#define SMEM_BYTES (OFF_CONS + 64)
static_assert(SMEM_BYTES <= 227 * 1024, "smem too big");

// Global scratch: ring-buffered hidden state, fp16, pair-permuted columns
__device__ __half g_h[HD][B_DIM][H_DIM];
// Init/final barrier (monotonic gen, replay-safe)
__device__ unsigned g_cnt[GB][32];
__device__ unsigned g_gen[GB][32];
// Dataflow flags: monotonic, one 128B line each
__device__ unsigned g_ready[GB][GC][32];
__device__ unsigned g_cons[GB][GC][32];

// Pair permutation within each 16-col group: unit u=(c&15)>>1 -> pos 2*(u&3)+(u>>2).
// Makes (col 2d, 2d+1) and (col 2d+8, 2d+9) adjacent 4B units -> one LDS.64 fragment pair.
__device__ __forceinline__ int perm16(int c) {
    int u = (c & 15) >> 1;
    int p = 2 * (u & 3) + (u >> 2);
    return (c & ~15) + 2 * p + (c & 1);
}

__device__ __forceinline__ float sigf(float x) {
    return __fdividef(1.0f, 1.0f + __expf(-x));
}
__device__ __forceinline__ float tanhfast(float x) {
    return 2.0f * __fdividef(1.0f, 1.0f + __expf(-2.0f * x)) - 1.0f;
}
__device__ __forceinline__ unsigned packh2(float a, float b) {
    __half2 h = __floats2half2_rn(a, b);
    return *reinterpret_cast<unsigned*>(&h);
}

__device__ __forceinline__ void mma16(float& d0, float& d1, float& d2, float& d3,
                                      unsigned a0, unsigned a1, unsigned a2, unsigned a3,
                                      unsigned b0, unsigned b1) {
    asm volatile(
        "mma.sync.aligned.m16n8k16.row.col.f32.f16.f16.f32 "
        "{%0,%1,%2,%3},{%4,%5,%6,%7},{%8,%9},{%0,%1,%2,%3};"
        : "+f"(d0), "+f"(d1), "+f"(d2), "+f"(d3)
        : "r"(a0), "r"(a1), "r"(a2), "r"(a3), "r"(b0), "r"(b1));
}

#define CP_ASYNC16(dst_u32, src) \
    asm volatile("cp.async.cg.shared.global [%0], [%1], 16;" :: "r"(dst_u32), "l"(src))
#define CP_COMMIT() asm volatile("cp.async.commit_group;")
#define CP_WAIT0()  asm volatile("cp.async.wait_group 0;")

__device__ __forceinline__ unsigned ld_acq(const unsigned* p) {
    unsigned v;
    asm volatile("ld.acquire.gpu.global.u32 %0, [%1];" : "=r"(v) : "l"(p) : "memory");
    return v;
}
__device__ __forceinline__ void st_rel(unsigned* p, unsigned v) {
    asm volatile("st.release.gpu.global.u32 [%0], %1;" :: "l"(p), "r"(v) : "memory");
}

__device__ __forceinline__ void gbar_arrive(int gb, unsigned target) {
    unsigned old;
    asm volatile("atom.acq_rel.gpu.global.add.u32 %0, [%1], %2;"
                 : "=r"(old) : "l"(&g_cnt[gb][0]), "r"(1u) : "memory");
    if (old == GC - 1u) {
        asm volatile("st.relaxed.gpu.global.u32 [%0], %1;" :: "l"(&g_cnt[gb][0]), "r"(0u) : "memory");
        st_rel(&g_gen[gb][0], target);
    }
}
__device__ __forceinline__ void gbar_wait(int gb, unsigned target) {
    while ((int)(ld_acq(&g_gen[gb][0]) - target) < 0) {}
}

__global__ void __launch_bounds__(NTHR, 1)
lstm_kernel(const int* __restrict__ inp, const int* __restrict__ lengths,
            const float* __restrict__ h0, const float* __restrict__ c0,
            const float* __restrict__ emb, const float* __restrict__ w_ih,
            const float* __restrict__ w_hh, const float* __restrict__ b_ih,
            const float* __restrict__ b_hh, const float* __restrict__ dec_w,
            float* __restrict__ out) {
    extern __shared__ char smc[];
    float*    sW    = (float*)(smc + OFF_W);      // [K_DIM][WT_ST] f32, init only
    __half*   sAh   = (__half*)(smc + OFF_A);     // [BT][ACT_STH]: emb cols 0..127, h 128..383
    float*    sG    = (float*)(smc + OFF_G);      // [KS][BT][G_ST] gate partials
    float*    sC    = (float*)(smc + OFF_C);      // [BT][HS]
    float*    sBias = (float*)(smc + OFF_BIAS);   // [GT]
    int*      sLen  = (int*)(smc + OFF_LEN);      // [BT]
    int*      sTok  = (int*)(smc + OFF_TOK);      // [BT]
    int*      sMax  = (int*)(smc + OFF_MAX);      // [1]
    unsigned* sRdyBase  = (unsigned*)(smc + OFF_RDY);   // [16]
    unsigned* sConsBase = (unsigned*)(smc + OFF_CONS);  // [16]

    const int tid = threadIdx.x;
    const int cta = blockIdx.x;
    const int gb = cta / GC;
    const int gc = cta % GC;
    const int b0 = gb * BT;

    // --- entry sampling (race-free before the init barrier) ---
    unsigned gen0 = 0;
    if (tid == 0) gen0 = ld_acq(&g_gen[gb][0]);
    if (tid < GC) {
        sRdyBase[tid]  = ld_acq(&g_ready[gb][tid][0]);
        sConsBase[tid] = ld_acq(&g_cons[gb][tid][0]);
    }

    // ---- one-time init: weights (f32), bias, lengths, c state, h[0] ----
    for (int idx = tid; idx < K_DIM * GT; idx += NTHR) {
        int k = idx / GT, c = idx % GT;
        int grow = (c / HS) * H_DIM + gc * HS + (c % HS);   // gate order i,f,g,o
        float w = (k < E_DIM) ? w_ih[grow * E_DIM + k] : w_hh[grow * H_DIM + (k - E_DIM)];
        sW[k * WT_ST + c] = w;
    }
    if (tid < GT) {
        int grow = (tid / HS) * H_DIM + gc * HS + (tid % HS);
        sBias[tid] = b_ih[grow] + b_hh[grow];
    }
    if (tid < BT) sLen[tid] = lengths[b0 + tid];
    for (int idx = tid; idx < BT * HS; idx += NTHR) {
        int m = idx / HS, u = idx % HS;
        sC[idx] = c0[(b0 + m) * H_DIM + gc * HS + u];
    }
    if (gc == 0) {
        for (int idx = tid; idx < BT * H_DIM; idx += NTHR) {
            int m = idx / H_DIM, u = idx % H_DIM;
            g_h[0][b0 + m][perm16(u)] = __float2half_rn(h0[(b0 + m) * H_DIM + u]);
        }
    }
    if (tid < BT) sTok[tid] = inp[b0 + tid];   // tokens for t = 0
    __syncthreads();
    if (tid == 0) {
        int mx = 0;
        for (int i = 0; i < BT; ++i) mx = max(mx, sLen[i]);
        sMax[0] = mx;
    }
    __syncthreads();
    const int ctaMax = sMax[0];                // uniform across the group (same rows)
    const unsigned rdyOwn  = sRdyBase[gc];
    const unsigned consOwn = sConsBase[gc];

    const int lane = tid & 31, warp = tid >> 5;
    const int ng = warp & 1;      // n half: 32 cols
    const int ks = warp >> 1;     // k slice

    // ---- preload B fragments (fp16 pairs) into registers (step-invariant) ----
    unsigned bw[NKT2][4][2];
    #pragma unroll
    for (int i = 0; i < NKT2; ++i) {
        int kt = (i < NXT2) ? (ks * NXT2 + i) : (8 + ks * NHT2 + (i - NXT2));
        int k0 = kt * 16 + 2 * (lane & 3);
        #pragma unroll
        for (int j = 0; j < 4; ++j) {
            int n = ng * 32 + j * 8 + (lane >> 2);
            bw[i][j][0] = packh2(sW[k0 * WT_ST + n],       sW[(k0 + 1) * WT_ST + n]);
            bw[i][j][1] = packh2(sW[(k0 + 8) * WT_ST + n], sW[(k0 + 9) * WT_ST + n]);
        }
    }

    // prologue: embedding columns of sA for t = 0 (permuted fp16 store)
    #pragma unroll
    for (int rep = 0; rep < (BT * 32) / NTHR; ++rep) {
        int i4 = tid + rep * NTHR;
        int m = i4 >> 5, q = i4 & 31;
        float4 v = __ldg(reinterpret_cast<const float4*>(emb + (size_t)sTok[m] * E_DIM) + q);
        int c = 4 * q, grp = c & ~15, u0 = (c & 15) >> 1;
        int p0 = 2 * (u0 & 3) + (u0 >> 2);
        int p1 = 2 * ((u0 + 1) & 3) + ((u0 + 1) >> 2);
        *(unsigned*)&sAh[m * ACT_STH + grp + 2 * p0] = packh2(v.x, v.y);
        *(unsigned*)&sAh[m * ACT_STH + grp + 2 * p1] = packh2(v.z, v.w);
    }
    // init barrier: h_0 + init visible group-wide (also orders flag sampling)
    __syncthreads();
    if (tid == 0) {
        gbar_arrive(gb, gen0 + 1u);
        gbar_wait(gb, gen0 + 1u);
    }
    __syncthreads();

    const char* Arow = (const char*)sAh + (lane >> 2) * ACT_STB + 8 * (lane & 3);

    // ---- recurrence: producer/consumer dataflow, no per-step barrier ----
    for (int t = 0; t < ctaMax; ++t) {
        const int rd = t & (HD - 1);           // slot holding h_t
        const int wr = (t + 1) & (HD - 1);     // slot receiving h_{t+1}

        // phase 1a: issue async h_t gather into sA halves 128..383 (16KB fp16)
        #pragma unroll
        for (int rep = 0; rep < (BT * 32) / NTHR; ++rep) {
            int i4 = tid + rep * NTHR;
            int m = i4 >> 5, q = i4 & 31;
            unsigned dst = (unsigned)__cvta_generic_to_shared(
                (char*)sAh + m * ACT_STB + 256 + q * 16);
            CP_ASYNC16(dst, (const char*)&g_h[rd][b0 + m][0] + q * 16);
        }
        CP_COMMIT();
        // prefetch next tokens (independent)
        if (tid < BT && t + 1 < ctaMax) sTok[tid] = inp[(t + 1) * B_DIM + b0 + tid];

        // phase 1b: x-part GEMM (emb prefetched last step) while gather flies
        float acc[2][4][4] = {};
        #pragma unroll
        for (int i = 0; i < NXT2; ++i) {
            const int kt = ks * NXT2 + i;
            uint2 v0[2], v1[2];
            #pragma unroll
            for (int mg = 0; mg < 2; ++mg) {
                v0[mg] = *(const uint2*)(Arow + (mg * 16) * ACT_STB + kt * 32);
                v1[mg] = *(const uint2*)(Arow + (mg * 16 + 8) * ACT_STB + kt * 32);
            }
            #pragma unroll
            for (int j = 0; j < 4; ++j) {
                mma16(acc[0][j][0], acc[0][j][1], acc[0][j][2], acc[0][j][3],
                      v0[0].x, v1[0].x, v0[0].y, v1[0].y, bw[i][j][0], bw[i][j][1]);
                mma16(acc[1][j][0], acc[1][j][1], acc[1][j][2], acc[1][j][3],
                      v0[1].x, v1[1].x, v0[1].y, v1[1].y, bw[i][j][0], bw[i][j][1]);
            }
        }
        CP_WAIT0();
        __syncthreads();
        // our gather of step t is complete -> release the slot for producers
        if (tid == 0) st_rel(&g_cons[gb][gc][0], consOwn + (unsigned)t + 1u);

        // phase 2: h-part GEMM (k16-tiles 8..23)
        #pragma unroll
        for (int i = 0; i < NHT2; ++i) {
            const int kt = 8 + ks * NHT2 + i;
            uint2 v0[2], v1[2];
            #pragma unroll
            for (int mg = 0; mg < 2; ++mg) {
                v0[mg] = *(const uint2*)(Arow + (mg * 16) * ACT_STB + kt * 32);
                v1[mg] = *(const uint2*)(Arow + (mg * 16 + 8) * ACT_STB + kt * 32);
            }
            #pragma unroll
            for (int j = 0; j < 4; ++j) {
                mma16(acc[0][j][0], acc[0][j][1], acc[0][j][2], acc[0][j][3],
                      v0[0].x, v1[0].x, v0[0].y, v1[0].y, bw[NXT2 + i][j][0], bw[NXT2 + i][j][1]);
                mma16(acc[1][j][0], acc[1][j][1], acc[1][j][2], acc[1][j][3],
                      v0[1].x, v1[1].x, v0[1].y, v1[1].y, bw[NXT2 + i][j][0], bw[NXT2 + i][j][1]);
            }
        }
        {   // spill gate partial tile to smem
            float* sGp = sG + ks * BT * G_ST;
            #pragma unroll
            for (int mg = 0; mg < 2; ++mg) {
                int r = mg * 16 + (lane >> 2);
                #pragma unroll
                for (int j = 0; j < 4; ++j) {
                    int cb = ng * 32 + j * 8 + 2 * (lane & 3);
                    sGp[r * G_ST + cb]           = acc[mg][j][0];
                    sGp[r * G_ST + cb + 1]       = acc[mg][j][1];
                    sGp[(r + 8) * G_ST + cb]     = acc[mg][j][2];
                    sGp[(r + 8) * G_ST + cb + 1] = acc[mg][j][3];
                }
            }
        }
        __syncthreads();

        // phase 3: elementwise cell update (writes h_{t+1} into ring slot wr)
        #pragma unroll
        for (int rep = 0; rep < (BT * HS) / NTHR; ++rep) {
            int idx = tid + rep * NTHR;
            int m = idx >> 4, u = idx & 15;
            float xi = sBias[u], xf = sBias[HS + u], xg = sBias[2 * HS + u], xo = sBias[3 * HS + u];
            #pragma unroll
            for (int p = 0; p < KS; ++p) {
                const float* gm = &sG[p * BT * G_ST + m * G_ST];
                xi += gm[u];
                xf += gm[HS + u];
                xg += gm[2 * HS + u];
                xo += gm[3 * HS + u];
            }
            float ii = sigf(xi), ff = sigf(xf), gg = tanhfast(xg), oo = sigf(xo);
            float c = ff * sC[idx] + ii * gg;
            sC[idx] = c;
            float h = oo * tanhfast(c);
            int b = b0 + m, ug = gc * HS + u;
            g_h[wr][b][perm16(ug)] = __float2half_rn(h);
            if (t == sLen[m] - 1) {
                out[B_DIM * O_DIM + (size_t)b * H_DIM + ug] = h;                          // last_h
                out[B_DIM * O_DIM + (size_t)B_DIM * H_DIM + (size_t)b * H_DIM + ug] = c;  // last_c
            }
        }
        __syncthreads();                      // all h STG issued CTA-wide
        // publish h_{t+1}
        if (tid == 0) st_rel(&g_ready[gb][gc][0], rdyOwn + (unsigned)t + 1u);

        // tail: warp 0 polls flags for step t+1; warps 1-7 prefill next embeddings
        if (t + 1 < ctaMax) {
            if (warp == 0) {
                unsigned i = lane & 15;
                const unsigned* ptr = (lane < 16) ? &g_ready[gb][i][0] : &g_cons[gb][i][0];
                int dcons = t + 3 - HD; if (dcons < 0) dcons = 0;
                unsigned tgt = (lane < 16) ? (sRdyBase[i] + (unsigned)(t + 1))
                                           : (sConsBase[i] + (unsigned)dcons);
                bool ok = false;
                do {
                    if (!ok) ok = ((int)(ld_acq(ptr) - tgt) >= 0);
                } while (!__all_sync(0xffffffffu, ok));
            } else {
                for (int i4 = tid - 32; i4 < BT * 32; i4 += NTHR - 32) {
                    int m = i4 >> 5, q = i4 & 31;
                    float4 v = __ldg(reinterpret_cast<const float4*>(emb + (size_t)sTok[m] * E_DIM) + q);
                    int c = 4 * q, grp = c & ~15, u0 = (c & 15) >> 1;
                    int p0 = 2 * (u0 & 3) + (u0 >> 2);
                    int p1 = 2 * ((u0 + 1) & 3) + ((u0 + 1) >> 2);
                    *(unsigned*)&sAh[m * ACT_STH + grp + 2 * p0] = packh2(v.x, v.y);
                    *(unsigned*)&sAh[m * ACT_STH + grp + 2 * p1] = packh2(v.z, v.w);
                }
            }
        }
        __syncthreads();                      // polls + prefill visible block-wide
    }

    // final join: all snapshots visible before the decoder
    if (tid == 0) {
        gbar_arrive(gb, gen0 + 2u);
        gbar_wait(gb, gen0 + 2u);
    }
    __syncthreads();

    // ---- decoder: decoded[b][o] = sigmoid(last_h[b] . dec_w[o]) ----
    if (gc == 0) {
        int pair = tid >> 2, part = tid & 3;   // 64 (b,o) pairs x 4-way split-k
        int m = pair >> 1, o = pair & 1;
        int b = b0 + m;
        const float* hrow = out + B_DIM * O_DIM + (size_t)b * H_DIM;
        const float* wrow = dec_w + o * H_DIM;
        float s = 0.f;
        #pragma unroll 16
        for (int u = part * 64; u < part * 64 + 64; ++u)
            s += __ldcg(hrow + u) * wrow[u];
        s += __shfl_xor_sync(0xffffffffu, s, 1);
        s += __shfl_xor_sync(0xffffffffu, s, 2);
        if (part == 0) out[b * O_DIM + o] = 1.0f / (1.0f + __expf(-s));
    }
}

extern "C" void kernel_launch(void* const* d_in, const int* in_sizes, int n_in,
                              void* d_out, int out_size) {
    const int*   inp = (const int*)d_in[0];
    const int*   len = (const int*)d_in[1];
    const float* h0  = (const float*)d_in[2];
    const float* c0  = (const float*)d_in[3];
    const float* emb = (const float*)d_in[4];
    const float* wih = (const float*)d_in[5];
    const float* whh = (const float*)d_in[6];
    const float* bih = (const float*)d_in[7];
    const float* bhh = (const float*)d_in[8];
    const float* dw  = (const float*)d_in[9];
    float* out = (float*)d_out;

    cudaFuncSetAttribute(lstm_kernel, cudaFuncAttributeMaxDynamicSharedMemorySize, SMEM_BYTES);
    lstm_kernel<<<NCTA, NTHR, SMEM_BYTES>>>(inp, len, h0, c0, emb, wih, whh, bih, bhh, dw, out);
}